// round 17
// baseline (speedup 1.0000x reference)
#include <cuda_runtime.h>
#include <cuda_fp16.h>
#include <cstdint>

// ============================================================================
// DQSN collapsed: out = A @ w2' + b2*(1-2^-16)
//   A[b,j] = sum_t spike_t(h_in[b,j]) * 2^(t-17),  h_in = x@w1' + b1
// R17: ONE persistent kernel (grid=296 = CTA slots) runs both GEMMs with an
// atomic tile queue + per-mblk readiness counters:
//   phase 1: g1 tiles (128x128, mblk-major) -> done[mblk]++ after fixup
//   phase 2: g2 tiles (64x64) spin on done[mblk]==8 then compute
// Early g2 tiles fill g1's wave-2 holes; inter-kernel drain eliminated; g2
// tail halves (64x64 tile ~ half the 128x64 tile-time). Both GEMMs are at the
// mma.sync HMMA issue ceiling (R10-R16), so remaining wins are scheduling.
// Spin-safety: all 296 CTAs co-resident; g2 spins only start after the g1
// queue is fully drained (every g1 tile assigned to a resident CTA).
// Math identical to R16 -> rel_err 2.4372e-4 unchanged.
// ============================================================================

#define MDIM 8192
#define IDIM 256
#define HDIM 1024
#define ODIM 256

// ---- GEMM1 geometry: BK=32 over physical K=256 (R15 winner) ----
#define G1_NK 8
#define G1_STRIDE 40                           // halves/row (80B)
#define G1_STAGE (512 * G1_STRIDE)             // xh128+xl128+wh128+wl128 rows
#define G1_SMEM (2 * G1_STAGE * 2)             // 81920 B
#define G1_TILES 512                           // (8192/128) * (1024/128)
// ---- GEMM2 geometry: 64x64 tiles, BK=64 over K=1024, 3 stages ----
#define G2_NK 16
#define G2_STRIDE 72                           // halves/row (144B)
#define G2_STAGE (128 * G2_STRIDE)             // 64 A rows + 64 W rows
#define G2_TILES 512                           // (8192/64) * (256/64)

#define FUSED_SMEM G1_SMEM                     // >= 3*G2_STAGE*2 (55296)
#define NUM_CTAS 296                           // 148 SMs x occ 2

#define FIX_CAP 2048
#define DELTA 1e-4f

// --------------------------- global scratch (no allocs) ---------------------
__device__ __align__(16) __half g_xh [(size_t)MDIM * IDIM];
__device__ __align__(16) __half g_xl [(size_t)MDIM * IDIM];
__device__ __align__(16) __half g_w1h[(size_t)HDIM * IDIM];
__device__ __align__(16) __half g_w1l[(size_t)HDIM * IDIM];
__device__ __align__(16) __half g_w2h[(size_t)ODIM * HDIM];
__device__ __align__(16) __half g_Ah [(size_t)MDIM * HDIM];
__device__ int g_q1, g_q2;
__device__ int g_done[64];                     // g1 n-blocks finished per mblk

// --------------------------- helpers ----------------------------------------
__device__ __forceinline__ void cp16(uint32_t s, const void* g) {
    asm volatile("cp.async.cg.shared.global [%0], [%1], 16;" :: "r"(s), "l"(g));
}
#define CP_COMMIT() asm volatile("cp.async.commit_group;" ::: "memory")
#define CP_WAIT0()  asm volatile("cp.async.wait_group 0;" ::: "memory")
#define CP_WAIT1()  asm volatile("cp.async.wait_group 1;" ::: "memory")

__device__ __forceinline__ void ldm_x4(uint32_t* r, uint32_t addr) {
    asm volatile("ldmatrix.sync.aligned.m8n8.x4.shared.b16 {%0,%1,%2,%3}, [%4];"
        : "=r"(r[0]), "=r"(r[1]), "=r"(r[2]), "=r"(r[3]) : "r"(addr));
}
__device__ __forceinline__ void mma_f16(float* c, const uint32_t* a, const uint32_t* b) {
    asm volatile(
        "mma.sync.aligned.m16n8k16.row.col.f32.f16.f16.f32 "
        "{%0,%1,%2,%3}, {%4,%5,%6,%7}, {%8,%9}, {%0,%1,%2,%3};"
        : "+f"(c[0]), "+f"(c[1]), "+f"(c[2]), "+f"(c[3])
        : "r"(a[0]), "r"(a[1]), "r"(a[2]), "r"(a[3]), "r"(b[0]), "r"(b[1]));
}
__device__ __forceinline__ uint32_t pack_h2(float a, float b) {
    __half2 t = __floats2half2_rn(a, b);
    return *reinterpret_cast<uint32_t*>(&t);
}

__device__ __forceinline__ float if_sim(float h) {
    float v = 0.0f, av = 0.0f, coef = 0x1p-16f;
#pragma unroll
    for (int t = 0; t < 16; t++) {
        v += h;
        const bool s = (v >= 1.0f);
        av = s ? (av + coef) : av;
        v = s ? 0.0f : v;
        coef += coef;
    }
    return av;
}
__device__ __forceinline__ float if_sim_flag(float h, bool& near) {
    float v = 0.0f, av = 0.0f, coef = 0x1p-16f;
#pragma unroll
    for (int t = 0; t < 16; t++) {
        v += h;
        near |= (fabsf(v - 1.0f) < DELTA);
        const bool s = (v >= 1.0f);
        av = s ? (av + coef) : av;
        v = s ? 0.0f : v;
        coef += coef;
    }
    return av;
}

// --------------------------- fused converter + counter reset -----------------
#define CONV_Q1 (MDIM * IDIM / 4)
#define CONV_Q2 (HDIM * IDIM / 4)
#define CONV_Q3 (ODIM * HDIM / 4)
#define CONV_QTOTAL (CONV_Q1 + CONV_Q2 + CONV_Q3)

__global__ __launch_bounds__(256)
void conv_all_kernel(const float* __restrict__ x, const float* __restrict__ w1,
                     const float* __restrict__ w2,
                     __half* __restrict__ xh, __half* __restrict__ xl,
                     __half* __restrict__ w1h, __half* __restrict__ w1l,
                     __half* __restrict__ w2h)
{
    if (blockIdx.x == 0) {                     // reset scheduler state (per launch)
        if (threadIdx.x == 0) { g_q1 = 0; g_q2 = 0; }
        if (threadIdx.x < 64) g_done[threadIdx.x] = 0;
    }
    const int i = blockIdx.x * blockDim.x + threadIdx.x;   // quad index
    if (i < CONV_Q1 + CONV_Q2) {
        const float* src;
        __half *dhi, *dlo;
        int idx;
        if (i < CONV_Q1) { src = x;  dhi = xh;  dlo = xl;  idx = i; }
        else             { src = w1; dhi = w1h; dlo = w1l; idx = i - CONV_Q1; }
        const float4 v = *reinterpret_cast<const float4*>(src + (size_t)idx * 4);
        const __half h0 = __float2half_rn(v.x), h1 = __float2half_rn(v.y);
        const __half h2 = __float2half_rn(v.z), h3 = __float2half_rn(v.w);
        uint2 hu, lu;
        hu.x = pack_h2(__half2float(h0), __half2float(h1));
        hu.y = pack_h2(__half2float(h2), __half2float(h3));
        lu.x = pack_h2(v.x - __half2float(h0), v.y - __half2float(h1));
        lu.y = pack_h2(v.z - __half2float(h2), v.w - __half2float(h3));
        reinterpret_cast<uint2*>(dhi)[idx] = hu;
        reinterpret_cast<uint2*>(dlo)[idx] = lu;
    } else {
        const int idx = i - CONV_Q1 - CONV_Q2;             // w2: hi only
        const float4 v = *reinterpret_cast<const float4*>(w2 + (size_t)idx * 4);
        uint2 hu;
        hu.x = pack_h2(v.x, v.y);
        hu.y = pack_h2(v.z, v.w);
        reinterpret_cast<uint2*>(w2h)[idx] = hu;
    }
}

// --------------------------- fused persistent GEMM kernel --------------------
__global__ __launch_bounds__(256, 2)
void fused_gemm(const __half* __restrict__ Xh, const __half* __restrict__ Xl,
                const __half* __restrict__ Wh, const __half* __restrict__ Wl,
                const float* __restrict__ b1, __half* __restrict__ Ah,
                const float* __restrict__ xf, const float* __restrict__ w1f,
                const __half* __restrict__ W2h, const float* __restrict__ b2,
                float* __restrict__ out)
{
    extern __shared__ __half sm[];
    __shared__ int s_cnt;
    __shared__ uint32_t s_list[FIX_CAP];
    __shared__ int s_tile;
    const uint32_t smb = (uint32_t)__cvta_generic_to_shared(sm);

    const int tid = threadIdx.x;
    const int lane = tid & 31;
    const int wid = tid >> 5;
    const int g = lane >> 3, lr = lane & 7;
    const int gq = lane >> 2, tq = lane & 3;

    // =================== phase 1: GEMM1 tiles (128x128) =====================
    {
        const int wm = (wid & 1) * 64, wn = (wid >> 1) * 32;  // 2x4 warp grid
        int axh_off[4], bwh_off[2];
#pragma unroll
        for (int ma = 0; ma < 4; ma++)
            axh_off[ma] = (wm + ma * 16 + (g & 1) * 8 + lr) * G1_STRIDE + (g >> 1) * 8;
#pragma unroll
        for (int nb = 0; nb < 2; nb++)
            bwh_off[nb] = (256 + wn + nb * 16 + (g >> 1) * 8 + lr) * G1_STRIDE + (g & 1) * 8;
        const int XL_OFF = 128 * G1_STRIDE;
        const int WL_OFF = 128 * G1_STRIDE;

        for (;;) {
            if (tid == 0) s_tile = atomicAdd(&g_q1, 1);
            __syncthreads();
            const int id = s_tile;
            if (id >= G1_TILES) break;
            const int mblk = id >> 3, nblk = id & 7;   // mblk-major: early ready
            if (tid == 0) s_cnt = 0;

            float acc[4][4][4];
#pragma unroll
            for (int i = 0; i < 4; i++)
#pragma unroll
                for (int j = 0; j < 4; j++)
#pragma unroll
                    for (int k = 0; k < 4; k++) acc[i][j][k] = 0.0f;

            auto load_stage = [&](int s, int kt) {
                const int k0 = kt * 32;
#pragma unroll
                for (int i = 0; i < 8; i++) {
                    const int c = tid + i * 256;
                    const int row = c >> 2, ch = (c & 3) * 8;
                    const __half* gp;
                    if (row < 128)
                        gp = Xh + (size_t)(mblk * 128 + row) * IDIM + k0 + ch;
                    else if (row < 256)
                        gp = Xl + (size_t)(mblk * 128 + (row - 128)) * IDIM + k0 + ch;
                    else if (row < 384)
                        gp = Wh + (size_t)(nblk * 128 + (row - 256)) * IDIM + k0 + ch;
                    else
                        gp = Wl + (size_t)(nblk * 128 + (row - 384)) * IDIM + k0 + ch;
                    cp16(smb + (uint32_t)(s * G1_STAGE + row * G1_STRIDE + ch) * 2, gp);
                }
            };

            load_stage(0, 0);
            CP_COMMIT();
            for (int kt = 0; kt < G1_NK; kt++) {
                CP_WAIT0();
                __syncthreads();
                if (kt + 1 < G1_NK) load_stage((kt + 1) & 1, kt + 1);
                CP_COMMIT();
                const uint32_t stg = smb + (uint32_t)((kt & 1) * G1_STAGE) * 2;
#pragma unroll
                for (int kk = 0; kk < 32; kk += 16) {
                    uint32_t a[4][4], bh[4][2], bl[4][2];
#pragma unroll
                    for (int ma = 0; ma < 4; ma++)
                        ldm_x4(a[ma], stg + (uint32_t)(axh_off[ma] + kk) * 2);
#pragma unroll
                    for (int nb = 0; nb < 2; nb++) {
                        uint32_t r[4];
                        ldm_x4(r, stg + (uint32_t)(bwh_off[nb] + kk) * 2);
                        bh[2 * nb][0] = r[0]; bh[2 * nb][1] = r[1];
                        bh[2 * nb + 1][0] = r[2]; bh[2 * nb + 1][1] = r[3];
                    }
#pragma unroll
                    for (int ma = 0; ma < 4; ma++)
#pragma unroll
                        for (int na = 0; na < 4; na++) mma_f16(acc[ma][na], a[ma], bh[na]);
#pragma unroll
                    for (int nb = 0; nb < 2; nb++) {
                        uint32_t r[4];
                        ldm_x4(r, stg + (uint32_t)(bwh_off[nb] + WL_OFF + kk) * 2);
                        bl[2 * nb][0] = r[0]; bl[2 * nb][1] = r[1];
                        bl[2 * nb + 1][0] = r[2]; bl[2 * nb + 1][1] = r[3];
                    }
#pragma unroll
                    for (int ma = 0; ma < 4; ma++)
#pragma unroll
                        for (int na = 0; na < 4; na++) mma_f16(acc[ma][na], a[ma], bl[na]);
#pragma unroll
                    for (int ma = 0; ma < 4; ma++)
                        ldm_x4(a[ma], stg + (uint32_t)(axh_off[ma] + XL_OFF + kk) * 2);
#pragma unroll
                    for (int ma = 0; ma < 4; ma++)
#pragma unroll
                        for (int na = 0; na < 4; na++) mma_f16(acc[ma][na], a[ma], bh[na]);
                }
            }

            // epilogue: +bias, IF sim + flag, write Ah
#pragma unroll
            for (int na = 0; na < 4; na++) {
                const int col = nblk * 128 + wn + na * 8 + 2 * tq;
                const float bb0 = __ldg(b1 + col);
                const float bb1 = __ldg(b1 + col + 1);
#pragma unroll
                for (int ma = 0; ma < 4; ma++) {
                    const int row0 = mblk * 128 + wm + ma * 16 + gq;
#pragma unroll
                    for (int rv = 0; rv < 2; rv++) {
                        const int row = row0 + rv * 8;
                        bool f0 = false, f1 = false;
                        const float a0 = if_sim_flag(acc[ma][na][rv * 2 + 0] + bb0, f0);
                        const float a1 = if_sim_flag(acc[ma][na][rv * 2 + 1] + bb1, f1);
                        const size_t pidx = (size_t)row * (HDIM / 2) + (col >> 1);
                        reinterpret_cast<uint32_t*>(Ah)[pidx] = pack_h2(a0, a1);
                        if (f0) {
                            const int idx = atomicAdd(&s_cnt, 1);
                            if (idx < FIX_CAP) s_list[idx] = (uint32_t)(row * 1024 + col);
                        }
                        if (f1) {
                            const int idx = atomicAdd(&s_cnt, 1);
                            if (idx < FIX_CAP) s_list[idx] = (uint32_t)(row * 1024 + col + 1);
                        }
                    }
                }
            }

            // in-CTA fixup (sequential fp32 FMA = reference rounding)
            __syncthreads();
            int n = s_cnt;
            n = n < FIX_CAP ? n : FIX_CAP;
            for (int i = tid; i < n; i += 256) {
                const uint32_t code = s_list[i];
                const int m = code >> 10, j = code & 1023;
                const float* xr = xf + (size_t)m * IDIM;
                const float* wr = w1f + (size_t)j * IDIM;
                float accs = 0.0f;
                for (int k = 0; k < IDIM; k++) accs = fmaf(xr[k], wr[k], accs);
                const float a = if_sim(accs + __ldg(b1 + j));
                Ah[(size_t)m * HDIM + j] = __float2half_rn(a);
            }

            // publish: all stores visible, then count this nblk done for mblk
            __threadfence();
            __syncthreads();
            if (tid == 0) atomicAdd(&g_done[mblk], 1);
        }
    }

    // =================== phase 2: GEMM2 tiles (64x64) =======================
    {
        const int wm = (wid & 3) * 16, wn = (wid >> 2) * 32;  // 4x2 warp grid
        const int a_off = (wm + (g & 1) * 8 + lr) * G2_STRIDE + (g >> 1) * 8;
        int b_off[2];
#pragma unroll
        for (int nb = 0; nb < 2; nb++)
            b_off[nb] = (64 + wn + nb * 16 + (g >> 1) * 8 + lr) * G2_STRIDE + (g & 1) * 8;

        const float BSCALE = 1.0f - 0x1p-16f;

        for (;;) {
            if (tid == 0) s_tile = atomicAdd(&g_q2, 1);
            __syncthreads();
            const int id = s_tile;
            if (id >= G2_TILES) break;
            const int tm = id >> 2, tn = id & 3;    // 64-row, 64-col tile
            // wait for the producing g1 mblk (128 rows -> mblk = tm/2)
            if (tid == 0) {
                while (atomicAdd(&g_done[tm >> 1], 0) < 8) __nanosleep(200);
            }
            __syncthreads();

            float acc[4][4];
#pragma unroll
            for (int j = 0; j < 4; j++)
#pragma unroll
                for (int k = 0; k < 4; k++) acc[j][k] = 0.0f;

            auto load_stage = [&](int s, int kt) {
                const int k0 = kt * 64;
#pragma unroll
                for (int i = 0; i < 4; i++) {      // 1024 chunks / 256 thr
                    const int c = tid + i * 256;
                    const int row = c >> 3, ch = (c & 7) * 8;
                    const __half* gp;
                    if (row < 64)
                        gp = Ah + (size_t)(tm * 64 + row) * HDIM + k0 + ch;
                    else
                        gp = W2h + (size_t)(tn * 64 + (row - 64)) * HDIM + k0 + ch;
                    cp16(smb + (uint32_t)(s * G2_STAGE + row * G2_STRIDE + ch) * 2, gp);
                }
            };

            load_stage(0, 0); CP_COMMIT();
            load_stage(1, 1); CP_COMMIT();
            for (int kt = 0; kt < G2_NK; kt++) {
                CP_WAIT1();
                __syncthreads();
                if (kt + 2 < G2_NK) load_stage((kt + 2) % 3, kt + 2);
                CP_COMMIT();
                const uint32_t stg = smb + (uint32_t)((kt % 3) * G2_STAGE) * 2;
#pragma unroll
                for (int kk = 0; kk < 64; kk += 16) {
                    uint32_t a[4], b[4][2];
                    ldm_x4(a, stg + (uint32_t)(a_off + kk) * 2);
#pragma unroll
                    for (int nb = 0; nb < 2; nb++) {
                        uint32_t r[4];
                        ldm_x4(r, stg + (uint32_t)(b_off[nb] + kk) * 2);
                        b[2 * nb][0] = r[0]; b[2 * nb][1] = r[1];
                        b[2 * nb + 1][0] = r[2]; b[2 * nb + 1][1] = r[3];
                    }
#pragma unroll
                    for (int na = 0; na < 4; na++) mma_f16(acc[na], a, b[na]);
                }
            }

            __syncthreads();   // smem reuse safety before next tile's loads
#pragma unroll
            for (int na = 0; na < 4; na++) {
                const int col = tn * 64 + wn + na * 8 + 2 * tq;
                const float bb0 = __ldg(b2 + col) * BSCALE;
                const float bb1 = __ldg(b2 + col + 1) * BSCALE;
                const int row0 = tm * 64 + wm + gq;
                *reinterpret_cast<float2*>(out + (size_t)row0 * ODIM + col) =
                    make_float2(acc[na][0] + bb0, acc[na][1] + bb1);
                *reinterpret_cast<float2*>(out + (size_t)(row0 + 8) * ODIM + col) =
                    make_float2(acc[na][2] + bb0, acc[na][3] + bb1);
            }
        }
    }
}

// --------------------------- launch -----------------------------------------
extern "C" void kernel_launch(void* const* d_in, const int* in_sizes, int n_in,
                              void* d_out, int out_size)
{
    const float* x  = (const float*)d_in[0];   // [8192, 256]
    const float* w1 = (const float*)d_in[1];   // [1024, 256]
    const float* b1 = (const float*)d_in[2];   // [1024]
    const float* w2 = (const float*)d_in[3];   // [256, 1024]
    const float* b2 = (const float*)d_in[4];   // [256]
    float* out = (float*)d_out;                // [8192, 256]

    __half *xh, *xl, *w1h, *w1l, *w2h, *Ah;
    cudaGetSymbolAddress((void**)&xh,  g_xh);
    cudaGetSymbolAddress((void**)&xl,  g_xl);
    cudaGetSymbolAddress((void**)&w1h, g_w1h);
    cudaGetSymbolAddress((void**)&w1l, g_w1l);
    cudaGetSymbolAddress((void**)&w2h, g_w2h);
    cudaGetSymbolAddress((void**)&Ah,  g_Ah);

    cudaFuncSetAttribute(fused_gemm,
                         cudaFuncAttributeMaxDynamicSharedMemorySize, FUSED_SMEM);

    conv_all_kernel<<<CONV_QTOTAL / 256, 256>>>(x, w1, w2, xh, xl, w1h, w1l, w2h);

    fused_gemm<<<NUM_CTAS, 256, FUSED_SMEM>>>(
        xh, xl, w1h, w1l, b1, Ah, x, w1, w2h, b2, out);
}